// round 1
// baseline (speedup 1.0000x reference)
#include <cuda_runtime.h>
#include <cstddef>

#define BB   2
#define TT   2048
#define CC   1024
#define NHH  16
#define HDD  64
#define DFFD 4096
#define ROWS (BB*TT)   // 4096

// ---------------- scratch (device globals; no allocations allowed) ----------
__device__ float g_q[ROWS*CC];
__device__ float g_k[ROWS*CC];
__device__ float g_v[ROWS*CC];
__device__ float g_a[ROWS*CC];
__device__ float g_h[ROWS*CC];
__device__ float g_m[(size_t)ROWS*DFFD];
__device__ float g_f[ROWS*CC];

// ---------------- SGEMM: C = A @ B + bias (optional ReLU) -------------------
// A [M,K] row-major, B [K,N] row-major, C [M,N] row-major.
// BM=BN=128, BK=8, 256 threads, 8x8 micro-tile per thread.
template<bool RELU>
__global__ __launch_bounds__(256) void sgemm_bias(
    const float* __restrict__ A, const float* __restrict__ B,
    const float* __restrict__ bias, float* __restrict__ C,
    int M, int N, int K)
{
    const int BM = 128, BN = 128, BK = 8;
    __shared__ float As[BK][BM];
    __shared__ float Bs[BK][BN];

    int tid  = threadIdx.x;
    int brow = blockIdx.y, bcol = blockIdx.x;
    int tx = tid % 16, ty = tid / 16;

    float acc[8][8];
    #pragma unroll
    for (int i = 0; i < 8; i++)
        #pragma unroll
        for (int j = 0; j < 8; j++) acc[i][j] = 0.f;

    int arow  = tid / 2;           // 0..127
    int acol  = (tid % 2) * 4;     // 0 or 4
    int brow8 = tid / 32;          // 0..7
    int bcol4 = (tid % 32) * 4;    // 0..124

    const float* Ap = A + (size_t)(brow * BM + arow) * K + acol;
    const float* Bp = B + (size_t)brow8 * N + bcol * BN + bcol4;

    for (int k0 = 0; k0 < K; k0 += BK) {
        float4 av = *(const float4*)(Ap + k0);
        float4 bv = *(const float4*)(Bp + (size_t)k0 * N);
        As[acol + 0][arow] = av.x;
        As[acol + 1][arow] = av.y;
        As[acol + 2][arow] = av.z;
        As[acol + 3][arow] = av.w;
        *(float4*)&Bs[brow8][bcol4] = bv;
        __syncthreads();
        #pragma unroll
        for (int kk = 0; kk < BK; kk++) {
            float a[8], b[8];
            #pragma unroll
            for (int i = 0; i < 8; i++) a[i] = As[kk][ty * 8 + i];
            #pragma unroll
            for (int j = 0; j < 8; j++) b[j] = Bs[kk][tx * 8 + j];
            #pragma unroll
            for (int i = 0; i < 8; i++)
                #pragma unroll
                for (int j = 0; j < 8; j++)
                    acc[i][j] += a[i] * b[j];
        }
        __syncthreads();
    }

    #pragma unroll
    for (int i = 0; i < 8; i++) {
        int r = brow * BM + ty * 8 + i;
        #pragma unroll
        for (int j = 0; j < 8; j += 4) {
            int c = bcol * BN + tx * 8 + j;
            float4 v;
            v.x = acc[i][j + 0] + bias[c + 0];
            v.y = acc[i][j + 1] + bias[c + 1];
            v.z = acc[i][j + 2] + bias[c + 2];
            v.w = acc[i][j + 3] + bias[c + 3];
            if (RELU) {
                v.x = fmaxf(v.x, 0.f); v.y = fmaxf(v.y, 0.f);
                v.z = fmaxf(v.z, 0.f); v.w = fmaxf(v.w, 0.f);
            }
            *(float4*)&C[(size_t)r * N + c] = v;
        }
    }
}

// ---------------- causal flash attention (fp32, online softmax) -------------
// Q,K,V,O viewed as [B*T, C] with head h occupying cols [h*64, h*64+64).
// Grid: (T/64, NH, B). 256 threads: thread = (row 0..63, seg 0..3),
// thread owns output cols seg*16..seg*16+15 of its q-row.
#define BQ  64
#define BKT 64

__global__ __launch_bounds__(256) void attn_kernel(
    const float* __restrict__ Q, const float* __restrict__ K,
    const float* __restrict__ V, float* __restrict__ O)
{
    extern __shared__ float sh[];
    float (*qs)[HDD + 4] = (float(*)[HDD + 4])(sh);
    float (*ks)[HDD + 4] = (float(*)[HDD + 4])(sh + 64 * 68);
    float (*vs)[HDD + 4] = (float(*)[HDD + 4])(sh + 2 * 64 * 68);
    float (*ss)[HDD + 4] = (float(*)[HDD + 4])(sh + 3 * 64 * 68);

    int qb = blockIdx.x, h = blockIdx.y, b = blockIdx.z;
    int tid = threadIdx.x;
    int row = tid >> 2;
    int seg = tid & 3;
    const float scale = 0.03125f;  // 1/sqrt(1024)

    const float* Qbase = Q + (size_t)(b * TT + qb * BQ) * CC + h * HDD;
    #pragma unroll
    for (int it = 0; it < 4; it++) {
        int idx = it * 256 + tid;
        int r = idx >> 4;
        int c = (idx & 15) * 4;
        *(float4*)&qs[r][c] = *(const float4*)&Qbase[(size_t)r * CC + c];
    }

    float acc[16];
    #pragma unroll
    for (int i = 0; i < 16; i++) acc[i] = 0.f;
    float mval = -1e30f, lval = 0.f;

    for (int kb = 0; kb <= qb; kb++) {
        const float* Kbase = K + (size_t)(b * TT + kb * BKT) * CC + h * HDD;
        const float* Vbase = V + (size_t)(b * TT + kb * BKT) * CC + h * HDD;
        __syncthreads();  // previous iter's ss/vs reads (and qs first iter) done
        #pragma unroll
        for (int it = 0; it < 4; it++) {
            int idx = it * 256 + tid;
            int r = idx >> 4;
            int c = (idx & 15) * 4;
            *(float4*)&ks[r][c] = *(const float4*)&Kbase[(size_t)r * CC + c];
            *(float4*)&vs[r][c] = *(const float4*)&Vbase[(size_t)r * CC + c];
        }
        __syncthreads();

        float sreg[16];
        #pragma unroll
        for (int j = 0; j < 16; j++) sreg[j] = 0.f;
        #pragma unroll 8
        for (int d = 0; d < HDD; d++) {
            float qv = qs[row][d];
            #pragma unroll
            for (int j = 0; j < 16; j++)
                sreg[j] += qv * ks[seg * 16 + j][d];
        }

        float pm = -1e30f;
        if (kb == qb) {
            #pragma unroll
            for (int j = 0; j < 16; j++) {
                int jj = seg * 16 + j;
                sreg[j] = (jj <= row) ? sreg[j] * scale : -1e30f;
                pm = fmaxf(pm, sreg[j]);
            }
        } else {
            #pragma unroll
            for (int j = 0; j < 16; j++) {
                sreg[j] *= scale;
                pm = fmaxf(pm, sreg[j]);
            }
        }
        #pragma unroll
        for (int o = 1; o < 4; o <<= 1)
            pm = fmaxf(pm, __shfl_xor_sync(0xffffffffu, pm, o));

        float mnew = fmaxf(mval, pm);
        float corr = __expf(mval - mnew);
        float psum = 0.f;
        #pragma unroll
        for (int j = 0; j < 16; j++) {
            float p = __expf(sreg[j] - mnew);
            ss[row][seg * 16 + j] = p;
            psum += p;
        }
        #pragma unroll
        for (int o = 1; o < 4; o <<= 1)
            psum += __shfl_xor_sync(0xffffffffu, psum, o);
        lval = lval * corr + psum;
        mval = mnew;
        #pragma unroll
        for (int i = 0; i < 16; i++) acc[i] *= corr;
        __syncthreads();

        // O += P @ V  (thread: row, cols seg*16..+15)
        for (int j = 0; j < BKT; j++) {
            float p = ss[row][j];
            #pragma unroll
            for (int dd = 0; dd < 16; dd++)
                acc[dd] += p * vs[j][seg * 16 + dd];
        }
    }

    float inv = 1.f / lval;
    float* Obase = O + (size_t)(b * TT + qb * BQ + row) * CC + h * HDD + seg * 16;
    #pragma unroll
    for (int dd = 0; dd < 16; dd += 4) {
        float4 v4;
        v4.x = acc[dd + 0] * inv;
        v4.y = acc[dd + 1] * inv;
        v4.z = acc[dd + 2] * inv;
        v4.w = acc[dd + 3] * inv;
        *(float4*)&Obase[dd] = v4;
    }
}

// ---------------- residual + layernorm: out = x + LN(x)*w -------------------
__global__ __launch_bounds__(256) void residual_ln(
    const float* __restrict__ X, const float* __restrict__ w,
    float* __restrict__ out)
{
    int rowi = blockIdx.x;
    const float* x = X + (size_t)rowi * CC;
    int tid = threadIdx.x;

    float4 v = *(const float4*)&x[tid * 4];
    float s  = v.x + v.y + v.z + v.w;
    float s2 = v.x * v.x + v.y * v.y + v.z * v.z + v.w * v.w;

    __shared__ float rs[32], rs2[32];
    #pragma unroll
    for (int o = 16; o > 0; o >>= 1) {
        s  += __shfl_xor_sync(0xffffffffu, s, o);
        s2 += __shfl_xor_sync(0xffffffffu, s2, o);
    }
    int wi = tid >> 5, li = tid & 31;
    if (li == 0) { rs[wi] = s; rs2[wi] = s2; }
    __syncthreads();
    if (wi == 0) {
        float a  = (li < 8) ? rs[li]  : 0.f;
        float a2 = (li < 8) ? rs2[li] : 0.f;
        #pragma unroll
        for (int o = 4; o > 0; o >>= 1) {
            a  += __shfl_xor_sync(0xffffffffu, a, o);
            a2 += __shfl_xor_sync(0xffffffffu, a2, o);
        }
        if (li == 0) { rs[0] = a; rs2[0] = a2; }
    }
    __syncthreads();
    float mu  = rs[0] * (1.f / CC);
    float var = rs2[0] * (1.f / CC) - mu * mu;
    float rstd = rsqrtf(var + 1e-5f);

    float4 wv = *(const float4*)&w[tid * 4];
    float4 o4;
    o4.x = v.x + (v.x - mu) * rstd * wv.x;
    o4.y = v.y + (v.y - mu) * rstd * wv.y;
    o4.z = v.z + (v.z - mu) * rstd * wv.z;
    o4.w = v.w + (v.w - mu) * rstd * wv.w;
    *(float4*)&out[(size_t)rowi * CC + tid * 4] = o4;
}

// ---------------- launch ----------------------------------------------------
extern "C" void kernel_launch(void* const* d_in, const int* in_sizes, int n_in,
                              void* d_out, int out_size)
{
    const float* x    = (const float*)d_in[0];
    const float* Wq   = (const float*)d_in[1];
    const float* bq   = (const float*)d_in[2];
    const float* Wk   = (const float*)d_in[3];
    const float* bk   = (const float*)d_in[4];
    const float* Wv   = (const float*)d_in[5];
    const float* bv   = (const float*)d_in[6];
    const float* W1   = (const float*)d_in[7];
    const float* b1   = (const float*)d_in[8];
    const float* W2   = (const float*)d_in[9];
    const float* b2   = (const float*)d_in[10];
    const float* ln_w = (const float*)d_in[11];
    float* out = (float*)d_out;

    float *pq, *pk, *pv, *pa, *ph, *pm, *pf;
    cudaGetSymbolAddress((void**)&pq, g_q);
    cudaGetSymbolAddress((void**)&pk, g_k);
    cudaGetSymbolAddress((void**)&pv, g_v);
    cudaGetSymbolAddress((void**)&pa, g_a);
    cudaGetSymbolAddress((void**)&ph, g_h);
    cudaGetSymbolAddress((void**)&pm, g_m);
    cudaGetSymbolAddress((void**)&pf, g_f);

    const int ATTN_SMEM = 4 * 64 * 68 * 4;  // 69632 B
    cudaFuncSetAttribute(attn_kernel,
                         cudaFuncAttributeMaxDynamicSharedMemorySize, ATTN_SMEM);

    dim3 t256(256);

    // QKV projections: [4096,1024] @ [1024,1024]
    dim3 gQKV(CC / 128, ROWS / 128);
    sgemm_bias<false><<<gQKV, t256>>>(x, Wq, bq, pq, ROWS, CC, CC);
    sgemm_bias<false><<<gQKV, t256>>>(x, Wk, bk, pk, ROWS, CC, CC);
    sgemm_bias<false><<<gQKV, t256>>>(x, Wv, bv, pv, ROWS, CC, CC);

    // attention
    dim3 gAttn(TT / BQ, NHH, BB);
    attn_kernel<<<gAttn, t256, ATTN_SMEM>>>(pq, pk, pv, pa);

    // h = a + LN(a)
    residual_ln<<<ROWS, t256>>>(pa, ln_w, ph);

    // FFN
    dim3 gF1(DFFD / 128, ROWS / 128);
    sgemm_bias<true><<<gF1, t256>>>(ph, W1, b1, pm, ROWS, DFFD, CC);
    dim3 gF2(CC / 128, ROWS / 128);
    sgemm_bias<false><<<gF2, t256>>>(pm, W2, b2, pf, ROWS, CC, DFFD);

    // out = f + LN(f)
    residual_ln<<<ROWS, t256>>>(pf, ln_w, out);
}

// round 2
// speedup vs baseline: 1.4056x; 1.4056x over previous
#include <cuda_runtime.h>
#include <cstdint>
#include <cstddef>

#define BB   2
#define TT   2048
#define CC   1024
#define NHH  16
#define HDD  64
#define DFFD 4096
#define ROWS (BB*TT)   // 4096

// ---------------- scratch (device globals; no allocations allowed) ----------
__device__ float g_q[ROWS*CC];
__device__ float g_k[ROWS*CC];
__device__ float g_v[ROWS*CC];
__device__ float g_a[ROWS*CC];
__device__ float g_h[ROWS*CC];
__device__ float g_m[(size_t)ROWS*DFFD];
__device__ float g_f[ROWS*CC];

// ---------------- helpers ----------------------------------------------------
__device__ __forceinline__ uint32_t sptr(const void* p) {
    return (uint32_t)__cvta_generic_to_shared(p);
}
__device__ __forceinline__ void cp_async16(uint32_t dst, const void* src) {
    asm volatile("cp.async.cg.shared.global [%0], [%1], 16;\n" :: "r"(dst), "l"(src));
}
__device__ __forceinline__ void cp_commit() {
    asm volatile("cp.async.commit_group;\n");
}
template<int N>
__device__ __forceinline__ void cp_wait() {
    asm volatile("cp.async.wait_group %0;\n" :: "n"(N));
}
__device__ __forceinline__ uint32_t f2tf32(float f) {
    uint32_t r;
    asm("cvt.rna.tf32.f32 %0, %1;\n" : "=r"(r) : "f"(f));
    return r;
}
__device__ __forceinline__ void mma_tf32(float d[4], const uint32_t a[4], const uint32_t b[2]) {
    asm volatile(
        "mma.sync.aligned.m16n8k8.row.col.f32.tf32.tf32.f32 "
        "{%0,%1,%2,%3},{%4,%5,%6,%7},{%8,%9},{%0,%1,%2,%3};\n"
        : "+f"(d[0]), "+f"(d[1]), "+f"(d[2]), "+f"(d[3])
        : "r"(a[0]), "r"(a[1]), "r"(a[2]), "r"(a[3]), "r"(b[0]), "r"(b[1]));
}

// ---------------- TF32 tensor-core GEMM: C = A @ B + bias (opt ReLU) --------
// A [M,K] rm, B [K,N] rm, C [M,N] rm. BM=BN=128, BK=32, 256 thr, 8 warps 2x4.
// Warp tile 64x32 -> 4x4 m16n8k8 mma tiles. cp.async double buffer.
#define GBM 128
#define GBN 128
#define GBK 32
#define ASTRIDE 36   // floats per A row in smem (conflict-free frag loads)
#define BSTRIDE 132  // floats per B row in smem
#define ABUF (GBM*ASTRIDE)   // 4608 floats
#define BBUF (GBK*BSTRIDE)   // 4224 floats
#define GEMM_SMEM ((2*ABUF + 2*BBUF)*4)  // 70656 B

template<bool RELU>
__global__ __launch_bounds__(256) void gemm_tf32(
    const float* __restrict__ A, const float* __restrict__ B,
    const float* __restrict__ bias, float* __restrict__ C,
    int M, int N, int K)
{
    extern __shared__ float sm[];
    float* smA = sm;              // [2][128][36]
    float* smB = sm + 2 * ABUF;   // [2][32][132]

    const int tid  = threadIdx.x;
    const int lane = tid & 31, warp = tid >> 5;
    const int wm = warp >> 2, wn = warp & 3;    // 2 x 4
    const int gr = lane >> 2, c4 = lane & 3;
    const int bm = blockIdx.y, bn = blockIdx.x;

    const int KT = K / GBK;

    // per-thread load assignments (4 chunks of 16B for A, 4 for B)
    // A tile: 128 rows x 8 chunks; B tile: 32 rows x 32 chunks
    int am[4], ak[4], bk_[4], bnq[4];
    uint32_t adst[2][4], bdst[2][4];
    #pragma unroll
    for (int i = 0; i < 4; i++) {
        int c = tid + i * 256;
        am[i] = c >> 3;  ak[i] = c & 7;
        bk_[i] = c >> 5; bnq[i] = c & 31;
        adst[0][i] = sptr(&smA[am[i] * ASTRIDE + ak[i] * 4]);
        adst[1][i] = sptr(&smA[ABUF + am[i] * ASTRIDE + ak[i] * 4]);
        bdst[0][i] = sptr(&smB[bk_[i] * BSTRIDE + bnq[i] * 4]);
        bdst[1][i] = sptr(&smB[BBUF + bk_[i] * BSTRIDE + bnq[i] * 4]);
    }
    const float* Abase = A + (size_t)(bm * GBM) * K;
    const float* Bbase = B + bn * GBN;

    float acc[4][4][4];
    #pragma unroll
    for (int mt = 0; mt < 4; mt++)
        #pragma unroll
        for (int nt = 0; nt < 4; nt++)
            #pragma unroll
            for (int r = 0; r < 4; r++) acc[mt][nt][r] = 0.f;

    // prologue: stage buffer 0
    #pragma unroll
    for (int i = 0; i < 4; i++)
        cp_async16(adst[0][i], Abase + (size_t)am[i] * K + ak[i] * 4);
    #pragma unroll
    for (int i = 0; i < 4; i++)
        cp_async16(bdst[0][i], Bbase + (size_t)bk_[i] * N + bnq[i] * 4);
    cp_commit();

    for (int kt = 0; kt < KT; kt++) {
        int p = kt & 1;
        if (kt + 1 < KT) {
            int koff = (kt + 1) * GBK;
            #pragma unroll
            for (int i = 0; i < 4; i++)
                cp_async16(adst[p ^ 1][i], Abase + (size_t)am[i] * K + koff + ak[i] * 4);
            #pragma unroll
            for (int i = 0; i < 4; i++)
                cp_async16(bdst[p ^ 1][i], Bbase + (size_t)(koff + bk_[i]) * N + bnq[i] * 4);
            cp_commit();
            cp_wait<1>();
        } else {
            cp_wait<0>();
        }
        __syncthreads();

        const float* Ap = smA + p * ABUF;
        const float* Bp = smB + p * BBUF;
        #pragma unroll
        for (int ks = 0; ks < 4; ks++) {
            int k0 = ks * 8;
            uint32_t afr[4][4], bfr[4][2];
            #pragma unroll
            for (int mt = 0; mt < 4; mt++) {
                int r0 = wm * 64 + mt * 16 + gr;
                afr[mt][0] = f2tf32(Ap[r0 * ASTRIDE + k0 + c4]);
                afr[mt][1] = f2tf32(Ap[(r0 + 8) * ASTRIDE + k0 + c4]);
                afr[mt][2] = f2tf32(Ap[r0 * ASTRIDE + k0 + c4 + 4]);
                afr[mt][3] = f2tf32(Ap[(r0 + 8) * ASTRIDE + k0 + c4 + 4]);
            }
            #pragma unroll
            for (int nt = 0; nt < 4; nt++) {
                int cc = wn * 32 + nt * 8 + gr;
                bfr[nt][0] = f2tf32(Bp[(k0 + c4) * BSTRIDE + cc]);
                bfr[nt][1] = f2tf32(Bp[(k0 + c4 + 4) * BSTRIDE + cc]);
            }
            #pragma unroll
            for (int mt = 0; mt < 4; mt++)
                #pragma unroll
                for (int nt = 0; nt < 4; nt++)
                    mma_tf32(acc[mt][nt], afr[mt], bfr[nt]);
        }
        __syncthreads();
    }

    // epilogue: bias (+ReLU), fp32 stores
    #pragma unroll
    for (int mt = 0; mt < 4; mt++) {
        int r0 = bm * GBM + wm * 64 + mt * 16 + gr;
        #pragma unroll
        for (int nt = 0; nt < 4; nt++) {
            int col = bn * GBN + wn * 32 + nt * 8 + 2 * c4;
            float bx = bias[col], by = bias[col + 1];
            float2 v0, v1;
            v0.x = acc[mt][nt][0] + bx; v0.y = acc[mt][nt][1] + by;
            v1.x = acc[mt][nt][2] + bx; v1.y = acc[mt][nt][3] + by;
            if (RELU) {
                v0.x = fmaxf(v0.x, 0.f); v0.y = fmaxf(v0.y, 0.f);
                v1.x = fmaxf(v1.x, 0.f); v1.y = fmaxf(v1.y, 0.f);
            }
            *(float2*)&C[(size_t)r0 * N + col] = v0;
            *(float2*)&C[(size_t)(r0 + 8) * N + col] = v1;
        }
    }
}

// ---------------- causal flash attention (fp32, online softmax) -------------
#define BQ  64
#define BKT 64

__global__ __launch_bounds__(256) void attn_kernel(
    const float* __restrict__ Q, const float* __restrict__ K,
    const float* __restrict__ V, float* __restrict__ O)
{
    extern __shared__ float sh[];
    float (*qs)[HDD + 4] = (float(*)[HDD + 4])(sh);
    float (*ks)[HDD + 4] = (float(*)[HDD + 4])(sh + 64 * 68);
    float (*vs)[HDD + 4] = (float(*)[HDD + 4])(sh + 2 * 64 * 68);
    float (*ss)[HDD + 4] = (float(*)[HDD + 4])(sh + 3 * 64 * 68);

    int qb = blockIdx.x, h = blockIdx.y, b = blockIdx.z;
    int tid = threadIdx.x;
    int row = tid >> 2;
    int seg = tid & 3;
    const float scale = 0.03125f;  // 1/sqrt(1024)

    const float* Qbase = Q + (size_t)(b * TT + qb * BQ) * CC + h * HDD;
    #pragma unroll
    for (int it = 0; it < 4; it++) {
        int idx = it * 256 + tid;
        int r = idx >> 4;
        int c = (idx & 15) * 4;
        *(float4*)&qs[r][c] = *(const float4*)&Qbase[(size_t)r * CC + c];
    }

    float acc[16];
    #pragma unroll
    for (int i = 0; i < 16; i++) acc[i] = 0.f;
    float mval = -1e30f, lval = 0.f;

    for (int kb = 0; kb <= qb; kb++) {
        const float* Kbase = K + (size_t)(b * TT + kb * BKT) * CC + h * HDD;
        const float* Vbase = V + (size_t)(b * TT + kb * BKT) * CC + h * HDD;
        __syncthreads();
        #pragma unroll
        for (int it = 0; it < 4; it++) {
            int idx = it * 256 + tid;
            int r = idx >> 4;
            int c = (idx & 15) * 4;
            *(float4*)&ks[r][c] = *(const float4*)&Kbase[(size_t)r * CC + c];
            *(float4*)&vs[r][c] = *(const float4*)&Vbase[(size_t)r * CC + c];
        }
        __syncthreads();

        float sreg[16];
        #pragma unroll
        for (int j = 0; j < 16; j++) sreg[j] = 0.f;
        #pragma unroll 8
        for (int d = 0; d < HDD; d++) {
            float qv = qs[row][d];
            #pragma unroll
            for (int j = 0; j < 16; j++)
                sreg[j] += qv * ks[seg * 16 + j][d];
        }

        float pm = -1e30f;
        if (kb == qb) {
            #pragma unroll
            for (int j = 0; j < 16; j++) {
                int jj = seg * 16 + j;
                sreg[j] = (jj <= row) ? sreg[j] * scale : -1e30f;
                pm = fmaxf(pm, sreg[j]);
            }
        } else {
            #pragma unroll
            for (int j = 0; j < 16; j++) {
                sreg[j] *= scale;
                pm = fmaxf(pm, sreg[j]);
            }
        }
        #pragma unroll
        for (int o = 1; o < 4; o <<= 1)
            pm = fmaxf(pm, __shfl_xor_sync(0xffffffffu, pm, o));

        float mnew = fmaxf(mval, pm);
        float corr = __expf(mval - mnew);
        float psum = 0.f;
        #pragma unroll
        for (int j = 0; j < 16; j++) {
            float p = __expf(sreg[j] - mnew);
            ss[row][seg * 16 + j] = p;
            psum += p;
        }
        #pragma unroll
        for (int o = 1; o < 4; o <<= 1)
            psum += __shfl_xor_sync(0xffffffffu, psum, o);
        lval = lval * corr + psum;
        mval = mnew;
        #pragma unroll
        for (int i = 0; i < 16; i++) acc[i] *= corr;
        __syncthreads();

        for (int j = 0; j < BKT; j++) {
            float p = ss[row][j];
            #pragma unroll
            for (int dd = 0; dd < 16; dd++)
                acc[dd] += p * vs[j][seg * 16 + dd];
        }
    }

    float inv = 1.f / lval;
    float* Obase = O + (size_t)(b * TT + qb * BQ + row) * CC + h * HDD + seg * 16;
    #pragma unroll
    for (int dd = 0; dd < 16; dd += 4) {
        float4 v4;
        v4.x = acc[dd + 0] * inv;
        v4.y = acc[dd + 1] * inv;
        v4.z = acc[dd + 2] * inv;
        v4.w = acc[dd + 3] * inv;
        *(float4*)&Obase[dd] = v4;
    }
}

// ---------------- residual + layernorm: out = x + LN(x)*w -------------------
__global__ __launch_bounds__(256) void residual_ln(
    const float* __restrict__ X, const float* __restrict__ w,
    float* __restrict__ out)
{
    int rowi = blockIdx.x;
    const float* x = X + (size_t)rowi * CC;
    int tid = threadIdx.x;

    float4 v = *(const float4*)&x[tid * 4];
    float s  = v.x + v.y + v.z + v.w;
    float s2 = v.x * v.x + v.y * v.y + v.z * v.z + v.w * v.w;

    __shared__ float rs[32], rs2[32];
    #pragma unroll
    for (int o = 16; o > 0; o >>= 1) {
        s  += __shfl_xor_sync(0xffffffffu, s, o);
        s2 += __shfl_xor_sync(0xffffffffu, s2, o);
    }
    int wi = tid >> 5, li = tid & 31;
    if (li == 0) { rs[wi] = s; rs2[wi] = s2; }
    __syncthreads();
    if (wi == 0) {
        float a  = (li < 8) ? rs[li]  : 0.f;
        float a2 = (li < 8) ? rs2[li] : 0.f;
        #pragma unroll
        for (int o = 4; o > 0; o >>= 1) {
            a  += __shfl_xor_sync(0xffffffffu, a, o);
            a2 += __shfl_xor_sync(0xffffffffu, a2, o);
        }
        if (li == 0) { rs[0] = a; rs2[0] = a2; }
    }
    __syncthreads();
    float mu  = rs[0] * (1.f / CC);
    float var = rs2[0] * (1.f / CC) - mu * mu;
    float rstd = rsqrtf(var + 1e-5f);

    float4 wv = *(const float4*)&w[tid * 4];
    float4 o4;
    o4.x = v.x + (v.x - mu) * rstd * wv.x;
    o4.y = v.y + (v.y - mu) * rstd * wv.y;
    o4.z = v.z + (v.z - mu) * rstd * wv.z;
    o4.w = v.w + (v.w - mu) * rstd * wv.w;
    *(float4*)&out[(size_t)rowi * CC + tid * 4] = o4;
}

// ---------------- launch ----------------------------------------------------
extern "C" void kernel_launch(void* const* d_in, const int* in_sizes, int n_in,
                              void* d_out, int out_size)
{
    const float* x    = (const float*)d_in[0];
    const float* Wq   = (const float*)d_in[1];
    const float* bq   = (const float*)d_in[2];
    const float* Wk   = (const float*)d_in[3];
    const float* bk   = (const float*)d_in[4];
    const float* Wv   = (const float*)d_in[5];
    const float* bv   = (const float*)d_in[6];
    const float* W1   = (const float*)d_in[7];
    const float* b1   = (const float*)d_in[8];
    const float* W2   = (const float*)d_in[9];
    const float* b2   = (const float*)d_in[10];
    const float* ln_w = (const float*)d_in[11];
    float* out = (float*)d_out;

    float *pq, *pk, *pv, *pa, *ph, *pm, *pf;
    cudaGetSymbolAddress((void**)&pq, g_q);
    cudaGetSymbolAddress((void**)&pk, g_k);
    cudaGetSymbolAddress((void**)&pv, g_v);
    cudaGetSymbolAddress((void**)&pa, g_a);
    cudaGetSymbolAddress((void**)&ph, g_h);
    cudaGetSymbolAddress((void**)&pm, g_m);
    cudaGetSymbolAddress((void**)&pf, g_f);

    const int ATTN_SMEM = 4 * 64 * 68 * 4;  // 69632 B
    cudaFuncSetAttribute(attn_kernel,
                         cudaFuncAttributeMaxDynamicSharedMemorySize, ATTN_SMEM);
    cudaFuncSetAttribute(gemm_tf32<false>,
                         cudaFuncAttributeMaxDynamicSharedMemorySize, GEMM_SMEM);
    cudaFuncSetAttribute(gemm_tf32<true>,
                         cudaFuncAttributeMaxDynamicSharedMemorySize, GEMM_SMEM);

    dim3 t256(256);

    // QKV projections: [4096,1024] @ [1024,1024]
    dim3 gQKV(CC / GBN, ROWS / GBM);
    gemm_tf32<false><<<gQKV, t256, GEMM_SMEM>>>(x, Wq, bq, pq, ROWS, CC, CC);
    gemm_tf32<false><<<gQKV, t256, GEMM_SMEM>>>(x, Wk, bk, pk, ROWS, CC, CC);
    gemm_tf32<false><<<gQKV, t256, GEMM_SMEM>>>(x, Wv, bv, pv, ROWS, CC, CC);

    // attention
    dim3 gAttn(TT / BQ, NHH, BB);
    attn_kernel<<<gAttn, t256, ATTN_SMEM>>>(pq, pk, pv, pa);

    // h = a + LN(a)
    residual_ln<<<ROWS, t256>>>(pa, ln_w, ph);

    // FFN
    dim3 gF1(DFFD / GBN, ROWS / GBM);
    gemm_tf32<true><<<gF1, t256, GEMM_SMEM>>>(ph, W1, b1, pm, ROWS, DFFD, CC);
    dim3 gF2(CC / GBN, ROWS / GBM);
    gemm_tf32<false><<<gF2, t256, GEMM_SMEM>>>(pm, W2, b2, pf, ROWS, CC, DFFD);

    // out = f + LN(f)
    residual_ln<<<ROWS, t256>>>(pf, ln_w, out);
}

// round 3
// speedup vs baseline: 6.1033x; 4.3421x over previous
#include <cuda_runtime.h>
#include <cstdint>
#include <cstddef>

#define BB   2
#define TT   2048
#define CC   1024
#define NHH  16
#define HDD  64
#define DFFD 4096
#define ROWS (BB*TT)   // 4096

// ---------------- scratch (device globals; no allocations allowed) ----------
__device__ float g_q[ROWS*CC];
__device__ float g_k[ROWS*CC];
__device__ float g_v[ROWS*CC];
__device__ float g_a[ROWS*CC];
__device__ float g_h[ROWS*CC];
__device__ float g_m[(size_t)ROWS*DFFD];
__device__ float g_f[ROWS*CC];

// ---------------- helpers ----------------------------------------------------
__device__ __forceinline__ uint32_t sptr(const void* p) {
    return (uint32_t)__cvta_generic_to_shared(p);
}
__device__ __forceinline__ void cp_async16(uint32_t dst, const void* src) {
    asm volatile("cp.async.cg.shared.global [%0], [%1], 16;\n" :: "r"(dst), "l"(src));
}
__device__ __forceinline__ void cp_commit() {
    asm volatile("cp.async.commit_group;\n");
}
template<int N>
__device__ __forceinline__ void cp_wait() {
    asm volatile("cp.async.wait_group %0;\n" :: "n"(N));
}
__device__ __forceinline__ uint32_t f2tf32(float f) {
    uint32_t r;
    asm("cvt.rna.tf32.f32 %0, %1;\n" : "=r"(r) : "f"(f));
    return r;
}
__device__ __forceinline__ void mma_tf32(float d[4], const uint32_t a[4], const uint32_t b[2]) {
    asm volatile(
        "mma.sync.aligned.m16n8k8.row.col.f32.tf32.tf32.f32 "
        "{%0,%1,%2,%3},{%4,%5,%6,%7},{%8,%9},{%0,%1,%2,%3};\n"
        : "+f"(d[0]), "+f"(d[1]), "+f"(d[2]), "+f"(d[3])
        : "r"(a[0]), "r"(a[1]), "r"(a[2]), "r"(a[3]), "r"(b[0]), "r"(b[1]));
}

// ---------------- TF32 tensor-core GEMM: C = A @ B + bias (opt ReLU) --------
#define GBM 128
#define GBN 128
#define GBK 32
#define ASTRIDE 36
#define BSTRIDE 132
#define ABUF (GBM*ASTRIDE)
#define BBUF (GBK*BSTRIDE)
#define GEMM_SMEM ((2*ABUF + 2*BBUF)*4)

template<bool RELU>
__global__ __launch_bounds__(256) void gemm_tf32(
    const float* __restrict__ A, const float* __restrict__ B,
    const float* __restrict__ bias, float* __restrict__ C,
    int M, int N, int K)
{
    extern __shared__ float sm[];
    float* smA = sm;
    float* smB = sm + 2 * ABUF;

    const int tid  = threadIdx.x;
    const int lane = tid & 31, warp = tid >> 5;
    const int wm = warp >> 2, wn = warp & 3;
    const int gr = lane >> 2, c4 = lane & 3;
    const int bm = blockIdx.y, bn = blockIdx.x;
    const int KT = K / GBK;

    int am[4], ak[4], bk_[4], bnq[4];
    uint32_t adst[2][4], bdst[2][4];
    #pragma unroll
    for (int i = 0; i < 4; i++) {
        int c = tid + i * 256;
        am[i] = c >> 3;  ak[i] = c & 7;
        bk_[i] = c >> 5; bnq[i] = c & 31;
        adst[0][i] = sptr(&smA[am[i] * ASTRIDE + ak[i] * 4]);
        adst[1][i] = sptr(&smA[ABUF + am[i] * ASTRIDE + ak[i] * 4]);
        bdst[0][i] = sptr(&smB[bk_[i] * BSTRIDE + bnq[i] * 4]);
        bdst[1][i] = sptr(&smB[BBUF + bk_[i] * BSTRIDE + bnq[i] * 4]);
    }
    const float* Abase = A + (size_t)(bm * GBM) * K;
    const float* Bbase = B + bn * GBN;

    float acc[4][4][4];
    #pragma unroll
    for (int mt = 0; mt < 4; mt++)
        #pragma unroll
        for (int nt = 0; nt < 4; nt++)
            #pragma unroll
            for (int r = 0; r < 4; r++) acc[mt][nt][r] = 0.f;

    #pragma unroll
    for (int i = 0; i < 4; i++)
        cp_async16(adst[0][i], Abase + (size_t)am[i] * K + ak[i] * 4);
    #pragma unroll
    for (int i = 0; i < 4; i++)
        cp_async16(bdst[0][i], Bbase + (size_t)bk_[i] * N + bnq[i] * 4);
    cp_commit();

    for (int kt = 0; kt < KT; kt++) {
        int p = kt & 1;
        if (kt + 1 < KT) {
            int koff = (kt + 1) * GBK;
            #pragma unroll
            for (int i = 0; i < 4; i++)
                cp_async16(adst[p ^ 1][i], Abase + (size_t)am[i] * K + koff + ak[i] * 4);
            #pragma unroll
            for (int i = 0; i < 4; i++)
                cp_async16(bdst[p ^ 1][i], Bbase + (size_t)(koff + bk_[i]) * N + bnq[i] * 4);
            cp_commit();
            cp_wait<1>();
        } else {
            cp_wait<0>();
        }
        __syncthreads();

        const float* Ap = smA + p * ABUF;
        const float* Bp = smB + p * BBUF;
        #pragma unroll
        for (int ks = 0; ks < 4; ks++) {
            int k0 = ks * 8;
            uint32_t afr[4][4], bfr[4][2];
            #pragma unroll
            for (int mt = 0; mt < 4; mt++) {
                int r0 = wm * 64 + mt * 16 + gr;
                afr[mt][0] = f2tf32(Ap[r0 * ASTRIDE + k0 + c4]);
                afr[mt][1] = f2tf32(Ap[(r0 + 8) * ASTRIDE + k0 + c4]);
                afr[mt][2] = f2tf32(Ap[r0 * ASTRIDE + k0 + c4 + 4]);
                afr[mt][3] = f2tf32(Ap[(r0 + 8) * ASTRIDE + k0 + c4 + 4]);
            }
            #pragma unroll
            for (int nt = 0; nt < 4; nt++) {
                int cc = wn * 32 + nt * 8 + gr;
                bfr[nt][0] = f2tf32(Bp[(k0 + c4) * BSTRIDE + cc]);
                bfr[nt][1] = f2tf32(Bp[(k0 + c4 + 4) * BSTRIDE + cc]);
            }
            #pragma unroll
            for (int mt = 0; mt < 4; mt++)
                #pragma unroll
                for (int nt = 0; nt < 4; nt++)
                    mma_tf32(acc[mt][nt], afr[mt], bfr[nt]);
        }
        __syncthreads();
    }

    #pragma unroll
    for (int mt = 0; mt < 4; mt++) {
        int r0 = bm * GBM + wm * 64 + mt * 16 + gr;
        #pragma unroll
        for (int nt = 0; nt < 4; nt++) {
            int col = bn * GBN + wn * 32 + nt * 8 + 2 * c4;
            float bx = bias[col], by = bias[col + 1];
            float2 v0, v1;
            v0.x = acc[mt][nt][0] + bx; v0.y = acc[mt][nt][1] + by;
            v1.x = acc[mt][nt][2] + bx; v1.y = acc[mt][nt][3] + by;
            if (RELU) {
                v0.x = fmaxf(v0.x, 0.f); v0.y = fmaxf(v0.y, 0.f);
                v1.x = fmaxf(v1.x, 0.f); v1.y = fmaxf(v1.y, 0.f);
            }
            *(float2*)&C[(size_t)r0 * N + col] = v0;
            *(float2*)&C[(size_t)(r0 + 8) * N + col] = v1;
        }
    }
}

// ---------------- MMA flash attention (tf32 tensor cores) -------------------
// CTA: 128 q-rows, 8 warps x 16 rows. KV blocks of 64. hd=64.
// Smem: Ks[2][64][68], Vs[2][64][72], Ps[8][16][68].
#define KSTR 68
#define VSTR 72
#define KBUF (64*KSTR)   // 4352
#define VBUF (64*VSTR)   // 4608
#define PBUF (16*KSTR)   // 1088
#define ATTN_SMEM ((2*KBUF + 2*VBUF + 8*PBUF)*4)  // 106496 B

__global__ __launch_bounds__(256, 2) void attn_mma(
    const float* __restrict__ Q, const float* __restrict__ K,
    const float* __restrict__ V, float* __restrict__ O)
{
    extern __shared__ float sh[];
    float* Ks = sh;
    float* Vs = sh + 2 * KBUF;
    float* Psw = sh + 2 * KBUF + 2 * VBUF + (threadIdx.x >> 5) * PBUF;

    const int tid  = threadIdx.x;
    const int lane = tid & 31, w = tid >> 5;
    const int gr = lane >> 2, c4 = lane & 3;
    const int qbi = gridDim.x - 1 - blockIdx.x;   // heavy blocks first
    const int h = blockIdx.y, b = blockIdx.z;

    const int r0g = qbi * 128 + w * 16 + gr;      // global seq row (lane row 0)
    const int r1g = r0g + 8;

    // ---- Q fragments, register resident for whole kernel ----
    const float* Qp0 = Q + (size_t)(b * TT + r0g) * CC + h * HDD;
    const float* Qp1 = Qp0 + 8 * CC;
    uint32_t qfr[8][4];
    #pragma unroll
    for (int kc = 0; kc < 8; kc++) {
        qfr[kc][0] = f2tf32(Qp0[kc * 8 + c4]);
        qfr[kc][1] = f2tf32(Qp1[kc * 8 + c4]);
        qfr[kc][2] = f2tf32(Qp0[kc * 8 + c4 + 4]);
        qfr[kc][3] = f2tf32(Qp1[kc * 8 + c4 + 4]);
    }

    float oacc[8][4];
    #pragma unroll
    for (int nt = 0; nt < 8; nt++)
        #pragma unroll
        for (int r = 0; r < 4; r++) oacc[nt][r] = 0.f;
    float m0 = -1e30f, m1 = -1e30f, l0 = 0.f, l1 = 0.f;

    // ---- cp.async assignments: 4 chunks of 16B each for K and V ----
    int krow[4], kcol[4];
    uint32_t kdst[2][4], vdst[2][4];
    #pragma unroll
    for (int i = 0; i < 4; i++) {
        int c = tid + i * 256;
        krow[i] = c >> 4; kcol[i] = c & 15;
        kdst[0][i] = sptr(&Ks[krow[i] * KSTR + kcol[i] * 4]);
        kdst[1][i] = sptr(&Ks[KBUF + krow[i] * KSTR + kcol[i] * 4]);
        vdst[0][i] = sptr(&Vs[krow[i] * VSTR + kcol[i] * 4]);
        vdst[1][i] = sptr(&Vs[VBUF + krow[i] * VSTR + kcol[i] * 4]);
    }
    const float* Kbase = K + (size_t)(b * TT) * CC + h * HDD;
    const float* Vbase = V + (size_t)(b * TT) * CC + h * HDD;

    const int kbmax = 2 * qbi + 1;

    // prologue: stage kb=0
    #pragma unroll
    for (int i = 0; i < 4; i++) {
        size_t off = (size_t)(krow[i]) * CC + kcol[i] * 4;
        cp_async16(kdst[0][i], Kbase + off);
        cp_async16(vdst[0][i], Vbase + off);
    }
    cp_commit();

    const float scl = 0.03125f;   // 1/sqrt(1024)

    for (int kt = 0; kt <= kbmax; kt++) {
        int p = kt & 1;
        if (kt < kbmax) {
            #pragma unroll
            for (int i = 0; i < 4; i++) {
                size_t off = (size_t)((kt + 1) * 64 + krow[i]) * CC + kcol[i] * 4;
                cp_async16(kdst[p ^ 1][i], Kbase + off);
                cp_async16(vdst[p ^ 1][i], Vbase + off);
            }
            cp_commit();
            cp_wait<1>();
        } else {
            cp_wait<0>();
        }
        __syncthreads();

        const float* Kp = Ks + p * KBUF;
        const float* Vp = Vs + p * VBUF;

        // ---- S = Q @ K^T ----
        float sacc[8][4];
        #pragma unroll
        for (int nt = 0; nt < 8; nt++)
            #pragma unroll
            for (int r = 0; r < 4; r++) sacc[nt][r] = 0.f;
        #pragma unroll
        for (int nt = 0; nt < 8; nt++) {
            const float* Kr = Kp + (nt * 8 + gr) * KSTR;
            #pragma unroll
            for (int kc = 0; kc < 8; kc++) {
                uint32_t bfr[2];
                bfr[0] = f2tf32(Kr[kc * 8 + c4]);
                bfr[1] = f2tf32(Kr[kc * 8 + c4 + 4]);
                mma_tf32(sacc[nt], qfr[kc], bfr);
            }
        }

        // ---- online softmax ----
        float pm0 = -1e30f, pm1 = -1e30f;
        const bool needmask = (kt >= 2 * qbi);
        #pragma unroll
        for (int nt = 0; nt < 8; nt++) {
            float s0 = sacc[nt][0] * scl, s1 = sacc[nt][1] * scl;
            float s2 = sacc[nt][2] * scl, s3 = sacc[nt][3] * scl;
            if (needmask) {
                int col = kt * 64 + nt * 8 + 2 * c4;
                if (col     > r0g) s0 = -1e30f;
                if (col + 1 > r0g) s1 = -1e30f;
                if (col     > r1g) s2 = -1e30f;
                if (col + 1 > r1g) s3 = -1e30f;
            }
            sacc[nt][0] = s0; sacc[nt][1] = s1;
            sacc[nt][2] = s2; sacc[nt][3] = s3;
            pm0 = fmaxf(pm0, fmaxf(s0, s1));
            pm1 = fmaxf(pm1, fmaxf(s2, s3));
        }
        #pragma unroll
        for (int o = 1; o < 4; o <<= 1) {
            pm0 = fmaxf(pm0, __shfl_xor_sync(0xffffffffu, pm0, o));
            pm1 = fmaxf(pm1, __shfl_xor_sync(0xffffffffu, pm1, o));
        }
        float mn0 = fmaxf(m0, pm0), mn1 = fmaxf(m1, pm1);
        float cr0 = __expf(m0 - mn0), cr1 = __expf(m1 - mn1);
        m0 = mn0; m1 = mn1;

        float ps0 = 0.f, ps1 = 0.f;
        #pragma unroll
        for (int nt = 0; nt < 8; nt++) {
            float p0 = __expf(sacc[nt][0] - m0);
            float p1 = __expf(sacc[nt][1] - m0);
            float p2 = __expf(sacc[nt][2] - m1);
            float p3 = __expf(sacc[nt][3] - m1);
            ps0 += p0 + p1; ps1 += p2 + p3;
            float2 a = {p0, p1}, bb = {p2, p3};
            *(float2*)&Psw[gr * KSTR + nt * 8 + 2 * c4] = a;
            *(float2*)&Psw[(gr + 8) * KSTR + nt * 8 + 2 * c4] = bb;
        }
        #pragma unroll
        for (int o = 1; o < 4; o <<= 1) {
            ps0 += __shfl_xor_sync(0xffffffffu, ps0, o);
            ps1 += __shfl_xor_sync(0xffffffffu, ps1, o);
        }
        l0 = l0 * cr0 + ps0;
        l1 = l1 * cr1 + ps1;
        #pragma unroll
        for (int nt = 0; nt < 8; nt++) {
            oacc[nt][0] *= cr0; oacc[nt][1] *= cr0;
            oacc[nt][2] *= cr1; oacc[nt][3] *= cr1;
        }
        __syncwarp();

        // ---- O += P @ V ----
        #pragma unroll
        for (int kc = 0; kc < 8; kc++) {
            uint32_t afr[4];
            afr[0] = f2tf32(Psw[gr * KSTR + kc * 8 + c4]);
            afr[1] = f2tf32(Psw[(gr + 8) * KSTR + kc * 8 + c4]);
            afr[2] = f2tf32(Psw[gr * KSTR + kc * 8 + c4 + 4]);
            afr[3] = f2tf32(Psw[(gr + 8) * KSTR + kc * 8 + c4 + 4]);
            const float* Vr0 = Vp + (kc * 8 + c4) * VSTR;
            const float* Vr1 = Vp + (kc * 8 + c4 + 4) * VSTR;
            #pragma unroll
            for (int nt = 0; nt < 8; nt++) {
                uint32_t bfr[2];
                bfr[0] = f2tf32(Vr0[nt * 8 + gr]);
                bfr[1] = f2tf32(Vr1[nt * 8 + gr]);
                mma_tf32(oacc[nt], afr, bfr);
            }
        }
        __syncthreads();
    }

    // ---- epilogue ----
    float inv0 = 1.f / l0, inv1 = 1.f / l1;
    float* Op0 = O + (size_t)(b * TT + r0g) * CC + h * HDD;
    float* Op1 = Op0 + 8 * CC;
    #pragma unroll
    for (int nt = 0; nt < 8; nt++) {
        float2 v0 = {oacc[nt][0] * inv0, oacc[nt][1] * inv0};
        float2 v1 = {oacc[nt][2] * inv1, oacc[nt][3] * inv1};
        *(float2*)&Op0[nt * 8 + 2 * c4] = v0;
        *(float2*)&Op1[nt * 8 + 2 * c4] = v1;
    }
}

// ---------------- residual + layernorm: out = x + LN(x)*w -------------------
__global__ __launch_bounds__(256) void residual_ln(
    const float* __restrict__ X, const float* __restrict__ w,
    float* __restrict__ out)
{
    int rowi = blockIdx.x;
    const float* x = X + (size_t)rowi * CC;
    int tid = threadIdx.x;

    float4 v = *(const float4*)&x[tid * 4];
    float s  = v.x + v.y + v.z + v.w;
    float s2 = v.x * v.x + v.y * v.y + v.z * v.z + v.w * v.w;

    __shared__ float rs[32], rs2[32];
    #pragma unroll
    for (int o = 16; o > 0; o >>= 1) {
        s  += __shfl_xor_sync(0xffffffffu, s, o);
        s2 += __shfl_xor_sync(0xffffffffu, s2, o);
    }
    int wi = tid >> 5, li = tid & 31;
    if (li == 0) { rs[wi] = s; rs2[wi] = s2; }
    __syncthreads();
    if (wi == 0) {
        float a  = (li < 8) ? rs[li]  : 0.f;
        float a2 = (li < 8) ? rs2[li] : 0.f;
        #pragma unroll
        for (int o = 4; o > 0; o >>= 1) {
            a  += __shfl_xor_sync(0xffffffffu, a, o);
            a2 += __shfl_xor_sync(0xffffffffu, a2, o);
        }
        if (li == 0) { rs[0] = a; rs2[0] = a2; }
    }
    __syncthreads();
    float mu  = rs[0] * (1.f / CC);
    float var = rs2[0] * (1.f / CC) - mu * mu;
    float rstd = rsqrtf(var + 1e-5f);

    float4 wv = *(const float4*)&w[tid * 4];
    float4 o4;
    o4.x = v.x + (v.x - mu) * rstd * wv.x;
    o4.y = v.y + (v.y - mu) * rstd * wv.y;
    o4.z = v.z + (v.z - mu) * rstd * wv.z;
    o4.w = v.w + (v.w - mu) * rstd * wv.w;
    *(float4*)&out[(size_t)rowi * CC + tid * 4] = o4;
}

// ---------------- launch ----------------------------------------------------
extern "C" void kernel_launch(void* const* d_in, const int* in_sizes, int n_in,
                              void* d_out, int out_size)
{
    const float* x    = (const float*)d_in[0];
    const float* Wq   = (const float*)d_in[1];
    const float* bq   = (const float*)d_in[2];
    const float* Wk   = (const float*)d_in[3];
    const float* bk   = (const float*)d_in[4];
    const float* Wv   = (const float*)d_in[5];
    const float* bv   = (const float*)d_in[6];
    const float* W1   = (const float*)d_in[7];
    const float* b1   = (const float*)d_in[8];
    const float* W2   = (const float*)d_in[9];
    const float* b2   = (const float*)d_in[10];
    const float* ln_w = (const float*)d_in[11];
    float* out = (float*)d_out;

    float *pq, *pk, *pv, *pa, *ph, *pm, *pf;
    cudaGetSymbolAddress((void**)&pq, g_q);
    cudaGetSymbolAddress((void**)&pk, g_k);
    cudaGetSymbolAddress((void**)&pv, g_v);
    cudaGetSymbolAddress((void**)&pa, g_a);
    cudaGetSymbolAddress((void**)&ph, g_h);
    cudaGetSymbolAddress((void**)&pm, g_m);
    cudaGetSymbolAddress((void**)&pf, g_f);

    cudaFuncSetAttribute(attn_mma,
                         cudaFuncAttributeMaxDynamicSharedMemorySize, ATTN_SMEM);
    cudaFuncSetAttribute(gemm_tf32<false>,
                         cudaFuncAttributeMaxDynamicSharedMemorySize, GEMM_SMEM);
    cudaFuncSetAttribute(gemm_tf32<true>,
                         cudaFuncAttributeMaxDynamicSharedMemorySize, GEMM_SMEM);

    dim3 t256(256);

    dim3 gQKV(CC / GBN, ROWS / GBM);
    gemm_tf32<false><<<gQKV, t256, GEMM_SMEM>>>(x, Wq, bq, pq, ROWS, CC, CC);
    gemm_tf32<false><<<gQKV, t256, GEMM_SMEM>>>(x, Wk, bk, pk, ROWS, CC, CC);
    gemm_tf32<false><<<gQKV, t256, GEMM_SMEM>>>(x, Wv, bv, pv, ROWS, CC, CC);

    dim3 gAttn(TT / 128, NHH, BB);
    attn_mma<<<gAttn, t256, ATTN_SMEM>>>(pq, pk, pv, pa);

    residual_ln<<<ROWS, t256>>>(pa, ln_w, ph);

    dim3 gF1(DFFD / GBN, ROWS / GBM);
    gemm_tf32<true><<<gF1, t256, GEMM_SMEM>>>(ph, W1, b1, pm, ROWS, DFFD, CC);
    dim3 gF2(CC / GBN, ROWS / GBM);
    gemm_tf32<false><<<gF2, t256, GEMM_SMEM>>>(pm, W2, b2, pf, ROWS, CC, DFFD);

    residual_ln<<<ROWS, t256>>>(pf, ln_w, out);
}